// round 4
// baseline (speedup 1.0000x reference)
#include <cuda_runtime.h>
#include <cstdint>

#define S_LEN   2048
#define BATCH   16
#define HID     512
#define IN_DIM  128
#define OUT_DIM 128
#define GRU_CTAS 128
#define JS       4          // h-dims per CTA (512/128)
#define HP       520        // padded smem row stride (floats)

// ---- scratch: device globals only (no allocation allowed) ----
__device__ float g_pz[(size_t)BATCH * S_LEN * HID];
__device__ float g_pr[(size_t)BATCH * S_LEN * HID];
__device__ float g_y [(size_t)BATCH * S_LEN * HID];
__device__ float g_h [BATCH * HID];
__device__ float g_rh[BATCH * HID];
__device__ unsigned long long g_barctr = 0;

// Monotonic ticket grid barrier. All 128 CTAs co-resident (<=148 SMs).
// Counter is a multiple of GRU_CTAS at every kernel entry/exit, so it is
// safe across launches and graph replays without reset.
__device__ __forceinline__ void grid_barrier() {
    __syncthreads();
    if (threadIdx.x == 0) {
        __threadfence();
        unsigned long long t = atomicAdd(&g_barctr, 1ULL);
        unsigned long long tgt = (t / GRU_CTAS + 1ULL) * GRU_CTAS;
        while (*((volatile unsigned long long*)&g_barctr) < tgt) { }
        __threadfence();
    }
    __syncthreads();
}

__global__ void init_h_kernel(const float* __restrict__ hst, int layer) {
    int i = blockIdx.x * blockDim.x + threadIdx.x;
    if (i < BATCH * HID)
        g_h[i] = hst[((i >> 9) << 10) + (layer << 9) + (i & 511)];
}

// C[M,N] = A[M,K] @ B[N,K]^T (+bias). 128x128 tile, BK=16, 8x8 microtile.
// All dims divide tiles exactly (M=32768, N in {512,128}, K in {128,512}).
__global__ __launch_bounds__(256, 2) void gemm_abt_kernel(
    const float* __restrict__ A, const float* __restrict__ B,
    const float* __restrict__ bias, float* __restrict__ C,
    int M, int N, int K)
{
    __shared__ __align__(16) float As[16][132];
    __shared__ __align__(16) float Bs[16][132];
    const int t = threadIdx.x, tx = t & 15, ty = t >> 4;
    const int m0 = blockIdx.y * 128, n0 = blockIdx.x * 128;
    const float* Ab = A + (size_t)m0 * K;
    const float* Bb = B + (size_t)n0 * K;

    float acc[8][8];
#pragma unroll
    for (int i = 0; i < 8; i++)
#pragma unroll
        for (int j = 0; j < 8; j++) acc[i][j] = 0.0f;

    for (int k0 = 0; k0 < K; k0 += 16) {
#pragma unroll
        for (int u = 0; u < 2; u++) {
            int f = t + 256 * u, r = f >> 2, c4 = f & 3;
            float4 va = *(const float4*)(Ab + (size_t)r * K + k0 + c4 * 4);
            As[c4*4+0][r] = va.x; As[c4*4+1][r] = va.y;
            As[c4*4+2][r] = va.z; As[c4*4+3][r] = va.w;
            float4 vb = *(const float4*)(Bb + (size_t)r * K + k0 + c4 * 4);
            Bs[c4*4+0][r] = vb.x; Bs[c4*4+1][r] = vb.y;
            Bs[c4*4+2][r] = vb.z; Bs[c4*4+3][r] = vb.w;
        }
        __syncthreads();
#pragma unroll
        for (int k = 0; k < 16; k++) {
            float rm[8], rn[8];
            *(float4*)&rm[0] = *(const float4*)&As[k][ty*8];
            *(float4*)&rm[4] = *(const float4*)&As[k][ty*8+4];
            *(float4*)&rn[0] = *(const float4*)&Bs[k][tx*8];
            *(float4*)&rn[4] = *(const float4*)&Bs[k][tx*8+4];
#pragma unroll
            for (int i = 0; i < 8; i++)
#pragma unroll
                for (int j = 0; j < 8; j++)
                    acc[i][j] = fmaf(rm[i], rn[j], acc[i][j]);
        }
        __syncthreads();
    }

    float bv[8];
#pragma unroll
    for (int j = 0; j < 8; j++) bv[j] = bias ? bias[n0 + tx*8 + j] : 0.0f;
#pragma unroll
    for (int i = 0; i < 8; i++) {
        float* cp = C + (size_t)(m0 + ty*8 + i) * N + n0 + tx*8;
        float4 o0, o1;
        o0.x = acc[i][0]+bv[0]; o0.y = acc[i][1]+bv[1];
        o0.z = acc[i][2]+bv[2]; o0.w = acc[i][3]+bv[3];
        o1.x = acc[i][4]+bv[4]; o1.y = acc[i][5]+bv[5];
        o1.z = acc[i][6]+bv[6]; o1.w = acc[i][7]+bv[7];
        *(float4*)cp = o0; *(float4*)(cp+4) = o1;
    }
}

// Persistent GRU layer. 128 CTAs x 256 thr; CTA owns j in [4*bid, 4*bid+4).
// Thread map per warp: jw=lane&3, ksub=lane>>2; warp: bq=w>>1 (batch group),
// khi=w&1 (k-half). Weight LDS broadcasts over jw; h LDS conflict-free.
__global__ __launch_bounds__(256, 1) void gru_layer_kernel(
    const float* __restrict__ xz, const float* __restrict__ xr,
    const float* __restrict__ Whz, const float* __restrict__ bhz,
    const float* __restrict__ Whr, const float* __restrict__ bhr,
    float* __restrict__ y, float* __restrict__ hf)
{
    extern __shared__ float sm[];
    float* hs  = sm;                 // [16][HP] full h
    float* rhs = hs  + BATCH * HP;   // [16][HP] full r*h
    float* wz  = rhs + BATCH * HP;   // [4][HP]
    float* wr  = wz  + JS * HP;      // [4][HP]
    float* pzp = wr  + JS * HP;      // [2][16][4]
    float* prp = pzp + 128;          // [2][16][4]
    float* zs  = prp + 128;          // [64]
    float* hos = zs  + 64;           // [64]
    float* xzs = hos + 64;           // [16][4]
    float* xrs = xzs + 64;           // [16][4]
    float* bz  = xrs + 64;           // [4]
    float* br  = bz  + 4;            // [4]

    const int tid  = threadIdx.x;
    const int j0   = blockIdx.x * JS;
    const int lane = tid & 31, wrp = tid >> 5;
    const int jw = lane & 3, ksub = lane >> 2;
    const int bq = wrp >> 1, khi = wrp & 1;
    const int fbase = ksub + 8 * khi;

    for (int idx = tid; idx < JS * HID; idx += 256) {
        int jj = idx >> 9, k = idx & 511;
        wz[jj*HP + k] = Whz[(size_t)(j0+jj)*HID + k];
        wr[jj*HP + k] = Whr[(size_t)(j0+jj)*HID + k];
    }
    if (tid < JS) { bz[tid] = bhz[j0+tid]; br[tid] = bhr[j0+tid]; }

    for (int step = 0; step < S_LEN; step++) {
        // -------- phase 1: z, r, publish r*h --------
        if (tid < BATCH) {
            size_t off = ((size_t)(tid * S_LEN + step) << 9) + j0;
            *(float4*)&xzs[tid*4] = *(const float4*)(xz + off);
            *(float4*)&xrs[tid*4] = *(const float4*)(xr + off);
        }
#pragma unroll
        for (int u = 0; u < 8; u++) {
            int f = tid + 256*u, b = f >> 7, c = f & 127;
            float4 v = __ldcg((const float4*)g_h + f);
            *(float4*)&hs[b*HP + c*4] = v;
        }
        __syncthreads();

        float az[4] = {0,0,0,0}, ar[4] = {0,0,0,0};
#pragma unroll
        for (int kk = 0; kk < 8; kk++) {
            int f4 = (fbase + 16*kk) * 4;
            float4 wzv = *(const float4*)&wz[jw*HP + f4];
            float4 wrv = *(const float4*)&wr[jw*HP + f4];
#pragma unroll
            for (int i = 0; i < 4; i++) {
                float4 hv = *(const float4*)&hs[(bq*4+i)*HP + f4];
                az[i] = fmaf(hv.x,wzv.x,az[i]); az[i] = fmaf(hv.y,wzv.y,az[i]);
                az[i] = fmaf(hv.z,wzv.z,az[i]); az[i] = fmaf(hv.w,wzv.w,az[i]);
                ar[i] = fmaf(hv.x,wrv.x,ar[i]); ar[i] = fmaf(hv.y,wrv.y,ar[i]);
                ar[i] = fmaf(hv.z,wrv.z,ar[i]); ar[i] = fmaf(hv.w,wrv.w,ar[i]);
            }
        }
#pragma unroll
        for (int off = 4; off < 32; off <<= 1)
#pragma unroll
            for (int i = 0; i < 4; i++) {
                az[i] += __shfl_xor_sync(0xffffffffu, az[i], off);
                ar[i] += __shfl_xor_sync(0xffffffffu, ar[i], off);
            }
        if (ksub == 0)
#pragma unroll
            for (int i = 0; i < 4; i++) {
                pzp[khi*64 + (bq*4+i)*4 + jw] = az[i];
                prp[khi*64 + (bq*4+i)*4 + jw] = ar[i];
            }
        __syncthreads();
        if (tid < 64) {
            int b = tid >> 2, jj = tid & 3;
            float pz = pzp[b*4+jj] + pzp[64+b*4+jj] + xzs[b*4+jj] + bz[jj];
            float pr = prp[b*4+jj] + prp[64+b*4+jj] + xrs[b*4+jj] + br[jj];
            float z = 1.0f / (1.0f + __expf(-pz));
            float r = 1.0f / (1.0f + __expf(-pr));
            float ho = hs[b*HP + j0 + jj];
            zs[tid] = z; hos[tid] = ho;
            __stcg(&g_rh[(b << 9) + j0 + jj], r * ho);
            __threadfence();
        }
        grid_barrier();

        // -------- phase 2: g, h_new --------
#pragma unroll
        for (int u = 0; u < 8; u++) {
            int f = tid + 256*u, b = f >> 7, c = f & 127;
            float4 v = __ldcg((const float4*)g_rh + f);
            *(float4*)&rhs[b*HP + c*4] = v;
        }
        __syncthreads();

        float ag[4] = {0,0,0,0};
#pragma unroll
        for (int kk = 0; kk < 8; kk++) {
            int f4 = (fbase + 16*kk) * 4;
            float4 wrv = *(const float4*)&wr[jw*HP + f4];
#pragma unroll
            for (int i = 0; i < 4; i++) {
                float4 hv = *(const float4*)&rhs[(bq*4+i)*HP + f4];
                ag[i] = fmaf(hv.x,wrv.x,ag[i]); ag[i] = fmaf(hv.y,wrv.y,ag[i]);
                ag[i] = fmaf(hv.z,wrv.z,ag[i]); ag[i] = fmaf(hv.w,wrv.w,ag[i]);
            }
        }
#pragma unroll
        for (int off = 4; off < 32; off <<= 1)
#pragma unroll
            for (int i = 0; i < 4; i++)
                ag[i] += __shfl_xor_sync(0xffffffffu, ag[i], off);
        if (ksub == 0)
#pragma unroll
            for (int i = 0; i < 4; i++)
                pzp[khi*64 + (bq*4+i)*4 + jw] = ag[i];
        __syncthreads();
        if (tid < 64) {
            int b = tid >> 2, jj = tid & 3;
            float pg = pzp[b*4+jj] + pzp[64+b*4+jj] + xrs[b*4+jj] + br[jj];
            float g = tanhf(pg);
            float z = zs[tid];
            float hn = z * hos[tid] + (1.0f - z) * g;
            __stcg(&g_h[(b << 9) + j0 + jj], hn);
            y[((size_t)(b * S_LEN + step) << 9) + j0 + jj] = hn;
            if (step == S_LEN - 1) hf[(b << 10) + j0 + jj] = hn;
            __threadfence();
        }
        grid_barrier();
    }
}

extern "C" void kernel_launch(void* const* d_in, const int* in_sizes, int n_in,
                              void* d_out, int out_size)
{
    (void)in_sizes; (void)n_in; (void)out_size;
    const float* x    = (const float*)d_in[0];
    const float* hst  = (const float*)d_in[1];
    const float* Wxz0 = (const float*)d_in[2];
    const float* Whz0 = (const float*)d_in[3];
    const float* bhz0 = (const float*)d_in[4];
    const float* Wxr0 = (const float*)d_in[5];
    const float* Whr0 = (const float*)d_in[6];
    const float* bhr0 = (const float*)d_in[7];
    const float* Wxz1 = (const float*)d_in[8];
    const float* Whz1 = (const float*)d_in[9];
    const float* bhz1 = (const float*)d_in[10];
    const float* Wxr1 = (const float*)d_in[11];
    const float* Whr1 = (const float*)d_in[12];
    const float* bhr1 = (const float*)d_in[13];
    const float* Why  = (const float*)d_in[14];
    const float* by   = (const float*)d_in[15];
    float* out = (float*)d_out;

    float *pz, *pr, *yb;
    cudaGetSymbolAddress((void**)&pz, g_pz);
    cudaGetSymbolAddress((void**)&pr, g_pr);
    cudaGetSymbolAddress((void**)&yb, g_y);

    const int GRU_SMEM = (2*BATCH*HP + 2*JS*HP + 2*128 + 4*64 + 8) * 4;
    cudaFuncSetAttribute(gru_layer_kernel,
                         cudaFuncAttributeMaxDynamicSharedMemorySize, GRU_SMEM);

    const int M = BATCH * S_LEN;                         // 32768
    float* hf = out + (size_t)BATCH * S_LEN * OUT_DIM;   // h_final [B,2,H]
    dim3 thr(256);

    // layer 0
    gemm_abt_kernel<<<dim3(HID/128, M/128), thr>>>(x, Wxz0, nullptr, pz, M, HID, IN_DIM);
    gemm_abt_kernel<<<dim3(HID/128, M/128), thr>>>(x, Wxr0, nullptr, pr, M, HID, IN_DIM);
    init_h_kernel<<<32, 256>>>(hst, 0);
    gru_layer_kernel<<<GRU_CTAS, thr, GRU_SMEM>>>(pz, pr, Whz0, bhz0, Whr0, bhr0, yb, hf);

    // layer 1 (input = y0; projections consume yb before gru overwrites it)
    gemm_abt_kernel<<<dim3(HID/128, M/128), thr>>>(yb, Wxz1, nullptr, pz, M, HID, HID);
    gemm_abt_kernel<<<dim3(HID/128, M/128), thr>>>(yb, Wxr1, nullptr, pr, M, HID, HID);
    init_h_kernel<<<32, 256>>>(hst, 1);
    gru_layer_kernel<<<GRU_CTAS, thr, GRU_SMEM>>>(pz, pr, Whz1, bhz1, Whr1, bhr1, yb, hf + HID);

    // output head: out = y1 @ Why^T + by
    gemm_abt_kernel<<<dim3(OUT_DIM/128, M/128), thr>>>(yb, Why, by, out, M, OUT_DIM, HID);
}

// round 5
// speedup vs baseline: 1.2842x; 1.2842x over previous
#include <cuda_runtime.h>
#include <cstdint>

#define S_LEN   2048
#define BATCH   16
#define HID     512
#define IN_DIM  128
#define OUT_DIM 128
#define NCTA    128
#define JS      4
#define HP      520

// ---- scratch: device globals only ----
__device__ float g_pz [(size_t)BATCH * S_LEN * HID];  // x @ Wxz0^T
__device__ float g_pr [(size_t)BATCH * S_LEN * HID];  // x @ Wxr0^T
__device__ float g_y0 [(size_t)BATCH * S_LEN * HID];  // layer-0 outputs
__device__ float g_y1 [(size_t)BATCH * S_LEN * HID];  // layer-1 outputs
__device__ float g_h0v[BATCH * HID];
__device__ float g_h1v[BATCH * HID];
__device__ float g_rh0[BATCH * HID];
__device__ float g_rh1[BATCH * HID];
__device__ unsigned int g_bar32;

// Grid barrier: release-arrive + per-warp acquire-poll. Counter is reset to 0
// by init_kernel before the persistent launch, so targets are (round#+1)*NCTA.
__device__ __forceinline__ void gbar(unsigned int target) {
    __syncthreads();
    if (threadIdx.x == 0) {
        __threadfence();
        unsigned int* p = &g_bar32;
        asm volatile("red.release.gpu.add.u32 [%0], %1;" :: "l"(p), "r"(1u) : "memory");
    }
    if ((threadIdx.x & 31) == 0) {
        unsigned int v;
        const unsigned int* p = &g_bar32;
        do {
            asm volatile("ld.acquire.gpu.u32 %0, [%1];" : "=r"(v) : "l"(p) : "memory");
        } while (v < target);
    }
    __syncwarp();
}

__global__ void init_kernel(const float* __restrict__ hst) {
    int i = blockIdx.x * blockDim.x + threadIdx.x;
    if (i == 0) g_bar32 = 0;
    if (i < BATCH * HID) {
        int b = i >> 9, j = i & 511;
        g_h0v[i] = hst[(b << 10) + j];
        g_h1v[i] = hst[(b << 10) + 512 + j];
    }
}

// C[M,N] = A[M,K] @ B[N,K]^T (+bias). 128x128 tile, BK=16, 8x8 microtile.
__global__ __launch_bounds__(256, 2) void gemm_abt_kernel(
    const float* __restrict__ A, const float* __restrict__ B,
    const float* __restrict__ bias, float* __restrict__ C,
    int M, int N, int K)
{
    __shared__ __align__(16) float As[16][132];
    __shared__ __align__(16) float Bs[16][132];
    const int t = threadIdx.x, tx = t & 15, ty = t >> 4;
    const int m0 = blockIdx.y * 128, n0 = blockIdx.x * 128;
    const float* Ab = A + (size_t)m0 * K;
    const float* Bb = B + (size_t)n0 * K;

    float acc[8][8];
#pragma unroll
    for (int i = 0; i < 8; i++)
#pragma unroll
        for (int j = 0; j < 8; j++) acc[i][j] = 0.0f;

    for (int k0 = 0; k0 < K; k0 += 16) {
#pragma unroll
        for (int u = 0; u < 2; u++) {
            int f = t + 256 * u, r = f >> 2, c4 = f & 3;
            float4 va = *(const float4*)(Ab + (size_t)r * K + k0 + c4 * 4);
            As[c4*4+0][r] = va.x; As[c4*4+1][r] = va.y;
            As[c4*4+2][r] = va.z; As[c4*4+3][r] = va.w;
            float4 vb = *(const float4*)(Bb + (size_t)r * K + k0 + c4 * 4);
            Bs[c4*4+0][r] = vb.x; Bs[c4*4+1][r] = vb.y;
            Bs[c4*4+2][r] = vb.z; Bs[c4*4+3][r] = vb.w;
        }
        __syncthreads();
#pragma unroll
        for (int k = 0; k < 16; k++) {
            float rm[8], rn[8];
            *(float4*)&rm[0] = *(const float4*)&As[k][ty*8];
            *(float4*)&rm[4] = *(const float4*)&As[k][ty*8+4];
            *(float4*)&rn[0] = *(const float4*)&Bs[k][tx*8];
            *(float4*)&rn[4] = *(const float4*)&Bs[k][tx*8+4];
#pragma unroll
            for (int i = 0; i < 8; i++)
#pragma unroll
                for (int j = 0; j < 8; j++)
                    acc[i][j] = fmaf(rm[i], rn[j], acc[i][j]);
        }
        __syncthreads();
    }
    float bv[8];
#pragma unroll
    for (int j = 0; j < 8; j++) bv[j] = bias ? bias[n0 + tx*8 + j] : 0.0f;
#pragma unroll
    for (int i = 0; i < 8; i++) {
        float* cp = C + (size_t)(m0 + ty*8 + i) * N + n0 + tx*8;
        float4 o0, o1;
        o0.x = acc[i][0]+bv[0]; o0.y = acc[i][1]+bv[1];
        o0.z = acc[i][2]+bv[2]; o0.w = acc[i][3]+bv[3];
        o1.x = acc[i][4]+bv[4]; o1.y = acc[i][5]+bv[5];
        o1.z = acc[i][6]+bv[6]; o1.w = acc[i][7]+bv[7];
        *(float4*)cp = o0; *(float4*)(cp+4) = o1;
    }
}

// ---- matvec helpers (per-warp map: jw=lane&3, ksub=lane>>2, bq=w>>1, khi=w&1) ----
__device__ __forceinline__ void mv_pair(const float* __restrict__ T,
                                        const float* __restrict__ wA,
                                        const float* __restrict__ wB,
                                        int jw, int fbase, int bq,
                                        float* aA, float* aB)
{
#pragma unroll
    for (int kk = 0; kk < 8; kk++) {
        const int f4 = (fbase + 16*kk) * 4;
        const float4 wa = *(const float4*)&wA[jw*HP + f4];
        const float4 wb = *(const float4*)&wB[jw*HP + f4];
#pragma unroll
        for (int i = 0; i < 4; i++) {
            const float4 hv = *(const float4*)&T[(bq*4+i)*HP + f4];
            aA[i] = fmaf(hv.x,wa.x,aA[i]); aA[i] = fmaf(hv.y,wa.y,aA[i]);
            aA[i] = fmaf(hv.z,wa.z,aA[i]); aA[i] = fmaf(hv.w,wa.w,aA[i]);
            aB[i] = fmaf(hv.x,wb.x,aB[i]); aB[i] = fmaf(hv.y,wb.y,aB[i]);
            aB[i] = fmaf(hv.z,wb.z,aB[i]); aB[i] = fmaf(hv.w,wb.w,aB[i]);
        }
    }
}
__device__ __forceinline__ void mv_one(const float* __restrict__ T,
                                       const float* __restrict__ wA,
                                       int jw, int fbase, int bq, float* aA)
{
#pragma unroll
    for (int kk = 0; kk < 8; kk++) {
        const int f4 = (fbase + 16*kk) * 4;
        const float4 wa = *(const float4*)&wA[jw*HP + f4];
#pragma unroll
        for (int i = 0; i < 4; i++) {
            const float4 hv = *(const float4*)&T[(bq*4+i)*HP + f4];
            aA[i] = fmaf(hv.x,wa.x,aA[i]); aA[i] = fmaf(hv.y,wa.y,aA[i]);
            aA[i] = fmaf(hv.z,wa.z,aA[i]); aA[i] = fmaf(hv.w,wa.w,aA[i]);
        }
    }
}
__device__ __forceinline__ void red_pair(float* pA, float* pB, float* aA, float* aB,
                                         int ksub, int khi, int bq, int jw)
{
#pragma unroll
    for (int off = 4; off < 32; off <<= 1)
#pragma unroll
        for (int i = 0; i < 4; i++) {
            aA[i] += __shfl_xor_sync(0xffffffffu, aA[i], off);
            aB[i] += __shfl_xor_sync(0xffffffffu, aB[i], off);
        }
    if (ksub == 0)
#pragma unroll
        for (int i = 0; i < 4; i++) {
            pA[khi*64 + (bq*4+i)*4 + jw] = aA[i];
            pB[khi*64 + (bq*4+i)*4 + jw] = aB[i];
        }
}
__device__ __forceinline__ void red_one(float* pA, float* aA,
                                        int ksub, int khi, int bq, int jw)
{
#pragma unroll
    for (int off = 4; off < 32; off <<= 1)
#pragma unroll
        for (int i = 0; i < 4; i++)
            aA[i] += __shfl_xor_sync(0xffffffffu, aA[i], off);
    if (ksub == 0)
#pragma unroll
        for (int i = 0; i < 4; i++)
            pA[khi*64 + (bq*4+i)*4 + jw] = aA[i];
}
__device__ __forceinline__ void load_tile(float* T, const float* g, int tid) {
#pragma unroll
    for (int u = 0; u < 8; u++) {
        int f = tid + 256*u, b = f >> 7, c = f & 127;
        float4 v = __ldcg((const float4*)g + f);
        *(float4*)&T[b*HP + c*4] = v;
    }
}
__device__ __forceinline__ void load_tile_y(float* T, const float* g, int step, int tid) {
#pragma unroll
    for (int u = 0; u < 8; u++) {
        int f = tid + 256*u, b = f >> 7, c = f & 127;
        float4 v = __ldcg((const float4*)(g + ((size_t)(b * S_LEN + step) << 9)) + c);
        *(float4*)&T[b*HP + c*4] = v;
    }
}

// ---- fused 2-layer pipelined GRU: 2049 rounds, layer1 lags layer0 by 1 ----
__global__ __launch_bounds__(256, 1) void gru_pipe_kernel(
    const float* __restrict__ pz0, const float* __restrict__ pr0,
    const float* __restrict__ Whz0, const float* __restrict__ bhz0,
    const float* __restrict__ Whr0, const float* __restrict__ bhr0,
    const float* __restrict__ Wxz1, const float* __restrict__ Whz1,
    const float* __restrict__ bhz1, const float* __restrict__ Wxr1,
    const float* __restrict__ Whr1, const float* __restrict__ bhr1,
    float* __restrict__ hf)
{
    extern __shared__ float sm[];
    float* T0   = sm;                  // [16][HP]
    float* T1   = T0 + BATCH*HP;
    float* T2   = T1 + BATCH*HP;
    float* wz0  = T2 + BATCH*HP;       // [4][HP] each
    float* wr0  = wz0 + JS*HP;
    float* wz1  = wr0 + JS*HP;
    float* wr1  = wz1 + JS*HP;
    float* wxz  = wr1 + JS*HP;
    float* wxr  = wxz + JS*HP;
    float* p0z  = wxr + JS*HP;         // [2][16][4] partials (6x)
    float* p0r  = p0z + 128;
    float* p1z  = p0r + 128;
    float* p1r  = p1z + 128;
    float* pxz  = p1r + 128;
    float* pxr  = pxz + 128;
    float* z0s  = pxr + 128;           // [64] small arrays
    float* h0s  = z0s + 64;
    float* z1s  = h0s + 64;
    float* h1s  = z1s + 64;
    float* axrs = h1s + 64;
    float* xz0s = axrs + 64;
    float* xr0s = xz0s + 64;
    float* bz0  = xr0s + 64;           // [4] each
    float* br0  = bz0 + 4;
    float* bz1  = br0 + 4;
    float* br1  = bz1 + 4;

    const int tid = threadIdx.x;
    const int j0  = blockIdx.x * JS;
    const int lane = tid & 31, wrp = tid >> 5;
    const int jw = lane & 3, ksub = lane >> 2;
    const int bq = wrp >> 1, khi = wrp & 1;
    const int fbase = ksub + 8 * khi;

    for (int idx = tid; idx < JS * HID; idx += 256) {
        int jj = idx >> 9, k = idx & 511;
        size_t w = (size_t)(j0 + jj) * HID + k;
        int s = jj * HP + k;
        wz0[s] = Whz0[w]; wr0[s] = Whr0[w];
        wz1[s] = Whz1[w]; wr1[s] = Whr1[w];
        wxz[s] = Wxz1[w]; wxr[s] = Wxr1[w];
    }
    if (tid < JS) {
        bz0[tid] = bhz0[j0+tid]; br0[tid] = bhr0[j0+tid];
        bz1[tid] = bhz1[j0+tid]; br1[tid] = bhr1[j0+tid];
    }

    unsigned int target = NCTA;
    for (int t = 0; t <= S_LEN; t++) {
        const bool L0 = (t < S_LEN);
        const bool L1 = (t >= 1);

        // ================= phase A: z, r (both layers) + layer1 projections ====
        if (L0) {
            if (tid < BATCH) {
                size_t off = ((size_t)(tid * S_LEN + t) << 9) + j0;
                *(float4*)&xz0s[tid*4] = *(const float4*)(pz0 + off);
                *(float4*)&xr0s[tid*4] = *(const float4*)(pr0 + off);
            }
            load_tile(T0, g_h0v, tid);
        }
        if (L1) {
            load_tile(T1, g_h1v, tid);
            load_tile_y(T2, g_y0, t - 1, tid);
        }
        __syncthreads();

        if (L0) {
            float a[4] = {0,0,0,0}, b[4] = {0,0,0,0};
            mv_pair(T0, wz0, wr0, jw, fbase, bq, a, b);
            red_pair(p0z, p0r, a, b, ksub, khi, bq, jw);
        }
        if (L1) {
            float a[4] = {0,0,0,0}, b[4] = {0,0,0,0};
            mv_pair(T1, wz1, wr1, jw, fbase, bq, a, b);
            red_pair(p1z, p1r, a, b, ksub, khi, bq, jw);
            float c[4] = {0,0,0,0}, d[4] = {0,0,0,0};
            mv_pair(T2, wxz, wxr, jw, fbase, bq, c, d);
            red_pair(pxz, pxr, c, d, ksub, khi, bq, jw);
        }
        __syncthreads();

        if (tid < 64) {
            const int b = tid >> 2, jj = tid & 3;
            if (L0) {
                float pz = p0z[b*4+jj] + p0z[64+b*4+jj] + xz0s[tid] + bz0[jj];
                float pr = p0r[b*4+jj] + p0r[64+b*4+jj] + xr0s[tid] + br0[jj];
                float z = 1.0f / (1.0f + __expf(-pz));
                float r = 1.0f / (1.0f + __expf(-pr));
                float ho = T0[b*HP + j0 + jj];
                z0s[tid] = z; h0s[tid] = ho;
                __stcg(&g_rh0[(b << 9) + j0 + jj], r * ho);
            }
            if (L1) {
                float axz = pxz[b*4+jj] + pxz[64+b*4+jj];
                float axr = pxr[b*4+jj] + pxr[64+b*4+jj];
                float pz = p1z[b*4+jj] + p1z[64+b*4+jj] + axz + bz1[jj];
                float pr = p1r[b*4+jj] + p1r[64+b*4+jj] + axr + br1[jj];
                float z = 1.0f / (1.0f + __expf(-pz));
                float r = 1.0f / (1.0f + __expf(-pr));
                float ho = T1[b*HP + j0 + jj];
                z1s[tid] = z; h1s[tid] = ho; axrs[tid] = axr;
                __stcg(&g_rh1[(b << 9) + j0 + jj], r * ho);
            }
        }
        gbar(target); target += NCTA;

        // ================= phase B: g, h_new (both layers) =====================
        if (L0) load_tile(T0, g_rh0, tid);
        if (L1) load_tile(T1, g_rh1, tid);
        __syncthreads();

        if (L0) {
            float a[4] = {0,0,0,0};
            mv_one(T0, wr0, jw, fbase, bq, a);
            red_one(p0z, a, ksub, khi, bq, jw);
        }
        if (L1) {
            float a[4] = {0,0,0,0};
            mv_one(T1, wr1, jw, fbase, bq, a);
            red_one(p1z, a, ksub, khi, bq, jw);
        }
        __syncthreads();

        if (tid < 64) {
            const int b = tid >> 2, jj = tid & 3;
            if (L0) {
                float pg = p0z[b*4+jj] + p0z[64+b*4+jj] + xr0s[tid] + br0[jj];
                float g = tanhf(pg);
                float z = z0s[tid];
                float hn = z * h0s[tid] + (1.0f - z) * g;
                __stcg(&g_h0v[(b << 9) + j0 + jj], hn);
                __stcg(&g_y0[((size_t)(b * S_LEN + t) << 9) + j0 + jj], hn);
                if (t == S_LEN - 1) hf[(b << 10) + j0 + jj] = hn;
            }
            if (L1) {
                float pg = p1z[b*4+jj] + p1z[64+b*4+jj] + axrs[tid] + br1[jj];
                float g = tanhf(pg);
                float z = z1s[tid];
                float hn = z * h1s[tid] + (1.0f - z) * g;
                __stcg(&g_h1v[(b << 9) + j0 + jj], hn);
                g_y1[((size_t)(b * S_LEN + (t-1)) << 9) + j0 + jj] = hn;
                if (t == S_LEN) hf[(b << 10) + 512 + j0 + jj] = hn;
            }
        }
        gbar(target); target += NCTA;
    }
}

extern "C" void kernel_launch(void* const* d_in, const int* in_sizes, int n_in,
                              void* d_out, int out_size)
{
    (void)in_sizes; (void)n_in; (void)out_size;
    const float* x    = (const float*)d_in[0];
    const float* hst  = (const float*)d_in[1];
    const float* Wxz0 = (const float*)d_in[2];
    const float* Whz0 = (const float*)d_in[3];
    const float* bhz0 = (const float*)d_in[4];
    const float* Wxr0 = (const float*)d_in[5];
    const float* Whr0 = (const float*)d_in[6];
    const float* bhr0 = (const float*)d_in[7];
    const float* Wxz1 = (const float*)d_in[8];
    const float* Whz1 = (const float*)d_in[9];
    const float* bhz1 = (const float*)d_in[10];
    const float* Wxr1 = (const float*)d_in[11];
    const float* Whr1 = (const float*)d_in[12];
    const float* bhr1 = (const float*)d_in[13];
    const float* Why  = (const float*)d_in[14];
    const float* by   = (const float*)d_in[15];
    float* out = (float*)d_out;

    float *pz, *pr, *y1;
    cudaGetSymbolAddress((void**)&pz, g_pz);
    cudaGetSymbolAddress((void**)&pr, g_pr);
    cudaGetSymbolAddress((void**)&y1, g_y1);

    const int GRU_SMEM = (3*BATCH*HP + 6*JS*HP + 6*128 + 7*64 + 16) * 4;
    static int smem_set = 0;
    cudaFuncSetAttribute(gru_pipe_kernel,
                         cudaFuncAttributeMaxDynamicSharedMemorySize, GRU_SMEM);
    (void)smem_set;

    const int M = BATCH * S_LEN;                        // 32768
    float* hf = out + (size_t)BATCH * S_LEN * OUT_DIM;  // h_final [B,2,H]
    dim3 thr(256);

    // layer-0 input projections (K = 128), off the critical path
    gemm_abt_kernel<<<dim3(HID/128, M/128), thr>>>(x, Wxz0, nullptr, pz, M, HID, IN_DIM);
    gemm_abt_kernel<<<dim3(HID/128, M/128), thr>>>(x, Wxr0, nullptr, pr, M, HID, IN_DIM);
    init_kernel<<<32, 256>>>(hst);

    // fused pipelined recurrence (both layers, 2049 rounds)
    gru_pipe_kernel<<<NCTA, thr, GRU_SMEM>>>(pz, pr,
        Whz0, bhz0, Whr0, bhr0,
        Wxz1, Whz1, bhz1, Wxr1, Whr1, bhr1, hf);

    // output head: out = y1 @ Why^T + by
    gemm_abt_kernel<<<dim3(OUT_DIM/128, M/128), thr>>>(y1, Why, by, out, M, OUT_DIM, HID);
}

// round 6
// speedup vs baseline: 1.6354x; 1.2735x over previous
#include <cuda_runtime.h>
#include <cstdint>

#define S_LEN   2048
#define BATCH   16
#define HID     512
#define IN_DIM  128
#define OUT_DIM 128
#define NCTA    128
#define JS      4
#define HP      520

// ---- scratch: device globals only ----
__device__ float g_pz [(size_t)BATCH * S_LEN * HID];  // x @ Wxz0^T
__device__ float g_pr [(size_t)BATCH * S_LEN * HID];  // x @ Wxr0^T
__device__ float g_y1 [(size_t)BATCH * S_LEN * HID];  // layer-1 outputs
__device__ float g_h0v[BATCH * HID];                  // h0 state (== y0[t-1] in round t)
__device__ float g_h1v[BATCH * HID];
__device__ float g_rh0[BATCH * HID];
__device__ float g_rh1[BATCH * HID];
__device__ unsigned int g_bar32;

// Grid barrier, CG grid.sync pattern: bar.sync -> thread0 red.release arrive +
// ld.acquire poll -> bar.sync broadcast. Single poller per CTA minimizes L2
// contention on the barrier line. Counter reset by init_kernel each call.
__device__ __forceinline__ void gbar(unsigned int target) {
    __syncthreads();
    if (threadIdx.x == 0) {
        unsigned int* p = &g_bar32;
        asm volatile("red.release.gpu.add.u32 [%0], %1;" :: "l"(p), "r"(1u) : "memory");
        unsigned int v;
        do {
            asm volatile("ld.acquire.gpu.u32 %0, [%1];" : "=r"(v) : "l"(p) : "memory");
        } while (v < target);
    }
    __syncthreads();
}

__global__ void init_kernel(const float* __restrict__ hst) {
    int i = blockIdx.x * blockDim.x + threadIdx.x;
    if (i == 0) g_bar32 = 0;
    if (i < BATCH * HID) {
        int b = i >> 9, j = i & 511;
        g_h0v[i] = hst[(b << 10) + j];
        g_h1v[i] = hst[(b << 10) + 512 + j];
    }
}

// C[M,N] = A[M,K] @ B[N,K]^T (+bias). 128x128 tile, BK=16, 8x8 microtile.
__global__ __launch_bounds__(256, 2) void gemm_abt_kernel(
    const float* __restrict__ A, const float* __restrict__ B,
    const float* __restrict__ bias, float* __restrict__ C,
    int M, int N, int K)
{
    __shared__ __align__(16) float As[16][132];
    __shared__ __align__(16) float Bs[16][132];
    const int t = threadIdx.x, tx = t & 15, ty = t >> 4;
    const int m0 = blockIdx.y * 128, n0 = blockIdx.x * 128;
    const float* Ab = A + (size_t)m0 * K;
    const float* Bb = B + (size_t)n0 * K;

    float acc[8][8];
#pragma unroll
    for (int i = 0; i < 8; i++)
#pragma unroll
        for (int j = 0; j < 8; j++) acc[i][j] = 0.0f;

    for (int k0 = 0; k0 < K; k0 += 16) {
#pragma unroll
        for (int u = 0; u < 2; u++) {
            int f = t + 256 * u, r = f >> 2, c4 = f & 3;
            float4 va = *(const float4*)(Ab + (size_t)r * K + k0 + c4 * 4);
            As[c4*4+0][r] = va.x; As[c4*4+1][r] = va.y;
            As[c4*4+2][r] = va.z; As[c4*4+3][r] = va.w;
            float4 vb = *(const float4*)(Bb + (size_t)r * K + k0 + c4 * 4);
            Bs[c4*4+0][r] = vb.x; Bs[c4*4+1][r] = vb.y;
            Bs[c4*4+2][r] = vb.z; Bs[c4*4+3][r] = vb.w;
        }
        __syncthreads();
#pragma unroll
        for (int k = 0; k < 16; k++) {
            float rm[8], rn[8];
            *(float4*)&rm[0] = *(const float4*)&As[k][ty*8];
            *(float4*)&rm[4] = *(const float4*)&As[k][ty*8+4];
            *(float4*)&rn[0] = *(const float4*)&Bs[k][tx*8];
            *(float4*)&rn[4] = *(const float4*)&Bs[k][tx*8+4];
#pragma unroll
            for (int i = 0; i < 8; i++)
#pragma unroll
                for (int j = 0; j < 8; j++)
                    acc[i][j] = fmaf(rm[i], rn[j], acc[i][j]);
        }
        __syncthreads();
    }
    float bv[8];
#pragma unroll
    for (int j = 0; j < 8; j++) bv[j] = bias ? bias[n0 + tx*8 + j] : 0.0f;
#pragma unroll
    for (int i = 0; i < 8; i++) {
        float* cp = C + (size_t)(m0 + ty*8 + i) * N + n0 + tx*8;
        float4 o0, o1;
        o0.x = acc[i][0]+bv[0]; o0.y = acc[i][1]+bv[1];
        o0.z = acc[i][2]+bv[2]; o0.w = acc[i][3]+bv[3];
        o1.x = acc[i][4]+bv[4]; o1.y = acc[i][5]+bv[5];
        o1.z = acc[i][6]+bv[6]; o1.w = acc[i][7]+bv[7];
        *(float4*)cp = o0; *(float4*)(cp+4) = o1;
    }
}

// ---- matvec helpers (per-warp map: jw=lane&3, ksub=lane>>2, bq=w>>1, khi=w&1) ----
__device__ __forceinline__ void mv_pair(const float* __restrict__ T,
                                        const float* __restrict__ wA,
                                        const float* __restrict__ wB,
                                        int jw, int fbase, int bq,
                                        float* aA, float* aB)
{
#pragma unroll
    for (int kk = 0; kk < 8; kk++) {
        const int f4 = (fbase + 16*kk) * 4;
        const float4 wa = *(const float4*)&wA[jw*HP + f4];
        const float4 wb = *(const float4*)&wB[jw*HP + f4];
#pragma unroll
        for (int i = 0; i < 4; i++) {
            const float4 hv = *(const float4*)&T[(bq*4+i)*HP + f4];
            aA[i] = fmaf(hv.x,wa.x,aA[i]); aA[i] = fmaf(hv.y,wa.y,aA[i]);
            aA[i] = fmaf(hv.z,wa.z,aA[i]); aA[i] = fmaf(hv.w,wa.w,aA[i]);
            aB[i] = fmaf(hv.x,wb.x,aB[i]); aB[i] = fmaf(hv.y,wb.y,aB[i]);
            aB[i] = fmaf(hv.z,wb.z,aB[i]); aB[i] = fmaf(hv.w,wb.w,aB[i]);
        }
    }
}
__device__ __forceinline__ void mv_one(const float* __restrict__ T,
                                       const float* __restrict__ wA,
                                       int jw, int fbase, int bq, float* aA)
{
#pragma unroll
    for (int kk = 0; kk < 8; kk++) {
        const int f4 = (fbase + 16*kk) * 4;
        const float4 wa = *(const float4*)&wA[jw*HP + f4];
#pragma unroll
        for (int i = 0; i < 4; i++) {
            const float4 hv = *(const float4*)&T[(bq*4+i)*HP + f4];
            aA[i] = fmaf(hv.x,wa.x,aA[i]); aA[i] = fmaf(hv.y,wa.y,aA[i]);
            aA[i] = fmaf(hv.z,wa.z,aA[i]); aA[i] = fmaf(hv.w,wa.w,aA[i]);
        }
    }
}
__device__ __forceinline__ void red_pair(float* pA, float* pB, float* aA, float* aB,
                                         int ksub, int khi, int bq, int jw)
{
#pragma unroll
    for (int off = 4; off < 32; off <<= 1)
#pragma unroll
        for (int i = 0; i < 4; i++) {
            aA[i] += __shfl_xor_sync(0xffffffffu, aA[i], off);
            aB[i] += __shfl_xor_sync(0xffffffffu, aB[i], off);
        }
    if (ksub == 0)
#pragma unroll
        for (int i = 0; i < 4; i++) {
            pA[khi*64 + (bq*4+i)*4 + jw] = aA[i];
            pB[khi*64 + (bq*4+i)*4 + jw] = aB[i];
        }
}
__device__ __forceinline__ void red_one(float* pA, float* aA,
                                        int ksub, int khi, int bq, int jw)
{
#pragma unroll
    for (int off = 4; off < 32; off <<= 1)
#pragma unroll
        for (int i = 0; i < 4; i++)
            aA[i] += __shfl_xor_sync(0xffffffffu, aA[i], off);
    if (ksub == 0)
#pragma unroll
        for (int i = 0; i < 4; i++)
            pA[khi*64 + (bq*4+i)*4 + jw] = aA[i];
}
__device__ __forceinline__ void load_tile(float* T, const float* g, int tid) {
#pragma unroll
    for (int u = 0; u < 8; u++) {
        int f = tid + 256*u, b = f >> 7, c = f & 127;
        float4 v = __ldcg((const float4*)g + f);
        *(float4*)&T[b*HP + c*4] = v;
    }
}

// ---- fused 2-layer pipelined GRU: 2049 rounds, layer1 lags layer0 by 1.
// Key identity: layer-1's input at round t is y0[t-1] == current g_h0v, so no
// separate y0 buffer or third tile load is needed.
__global__ __launch_bounds__(256, 1) void gru_pipe_kernel(
    const float* __restrict__ pz0, const float* __restrict__ pr0,
    const float* __restrict__ Whz0, const float* __restrict__ bhz0,
    const float* __restrict__ Whr0, const float* __restrict__ bhr0,
    const float* __restrict__ Wxz1, const float* __restrict__ Whz1,
    const float* __restrict__ bhz1, const float* __restrict__ Wxr1,
    const float* __restrict__ Whr1, const float* __restrict__ bhr1,
    float* __restrict__ hf)
{
    extern __shared__ float sm[];
    float* T0   = sm;                  // [16][HP]  h0 / rh0
    float* T1   = T0 + BATCH*HP;       // [16][HP]  h1 / rh1
    float* wz0  = T1 + BATCH*HP;       // [4][HP] x6 weight slices
    float* wr0  = wz0 + JS*HP;
    float* wz1  = wr0 + JS*HP;
    float* wr1  = wz1 + JS*HP;
    float* wxz  = wr1 + JS*HP;
    float* wxr  = wxz + JS*HP;
    float* p0z  = wxr + JS*HP;         // [2][16][4] partials x6
    float* p0r  = p0z + 128;
    float* p1z  = p0r + 128;
    float* p1r  = p1z + 128;
    float* pxz  = p1r + 128;
    float* pxr  = pxz + 128;
    float* z0s  = pxr + 128;           // [64] each
    float* h0s  = z0s + 64;
    float* z1s  = h0s + 64;
    float* h1s  = z1s + 64;
    float* axrs = h1s + 64;
    float* xz0s = axrs + 64;
    float* xr0s = xz0s + 64;
    float* bz0  = xr0s + 64;           // [4] each
    float* br0  = bz0 + 4;
    float* bz1  = br0 + 4;
    float* br1  = bz1 + 4;

    const int tid = threadIdx.x;
    const int j0  = blockIdx.x * JS;
    const int lane = tid & 31, wrp = tid >> 5;
    const int jw = lane & 3, ksub = lane >> 2;
    const int bq = wrp >> 1, khi = wrp & 1;
    const int fbase = ksub + 8 * khi;

    for (int idx = tid; idx < JS * HID; idx += 256) {
        int jj = idx >> 9, k = idx & 511;
        size_t w = (size_t)(j0 + jj) * HID + k;
        int s = jj * HP + k;
        wz0[s] = Whz0[w]; wr0[s] = Whr0[w];
        wz1[s] = Whz1[w]; wr1[s] = Whr1[w];
        wxz[s] = Wxz1[w]; wxr[s] = Wxr1[w];
    }
    if (tid < JS) {
        bz0[tid] = bhz0[j0+tid]; br0[tid] = bhr0[j0+tid];
        bz1[tid] = bhz1[j0+tid]; br1[tid] = bhr1[j0+tid];
    }

    unsigned int target = NCTA;
    for (int t = 0; t <= S_LEN; t++) {
        const bool L0 = (t < S_LEN);
        const bool L1 = (t >= 1);

        // ===== phase A: z, r (both layers) + layer1 input projections =====
        // T0 <- h0 (== y0[t-1]); needed by L0 matvecs AND L1 projections.
        load_tile(T0, g_h0v, tid);
        if (L1) load_tile(T1, g_h1v, tid);
        if (L0 && tid < BATCH) {
            size_t off = ((size_t)(tid * S_LEN + t) << 9) + j0;
            *(float4*)&xz0s[tid*4] = *(const float4*)(pz0 + off);
            *(float4*)&xr0s[tid*4] = *(const float4*)(pr0 + off);
        }
        __syncthreads();

        if (L0) {
            float a[4] = {0,0,0,0}, b[4] = {0,0,0,0};
            mv_pair(T0, wz0, wr0, jw, fbase, bq, a, b);
            red_pair(p0z, p0r, a, b, ksub, khi, bq, jw);
        }
        if (L1) {
            float a[4] = {0,0,0,0}, b[4] = {0,0,0,0};
            mv_pair(T1, wz1, wr1, jw, fbase, bq, a, b);
            red_pair(p1z, p1r, a, b, ksub, khi, bq, jw);
            float c[4] = {0,0,0,0}, d[4] = {0,0,0,0};
            mv_pair(T0, wxz, wxr, jw, fbase, bq, c, d);   // input = y0[t-1]
            red_pair(pxz, pxr, c, d, ksub, khi, bq, jw);
        }
        __syncthreads();

        if (tid < 64) {
            const int b = tid >> 2, jj = tid & 3;
            if (L0) {
                float pz = p0z[b*4+jj] + p0z[64+b*4+jj] + xz0s[tid] + bz0[jj];
                float pr = p0r[b*4+jj] + p0r[64+b*4+jj] + xr0s[tid] + br0[jj];
                float z = 1.0f / (1.0f + __expf(-pz));
                float r = 1.0f / (1.0f + __expf(-pr));
                float ho = T0[b*HP + j0 + jj];
                z0s[tid] = z; h0s[tid] = ho;
                __stcg(&g_rh0[(b << 9) + j0 + jj], r * ho);
            }
            if (L1) {
                float axz = pxz[b*4+jj] + pxz[64+b*4+jj];
                float axr = pxr[b*4+jj] + pxr[64+b*4+jj];
                float pz = p1z[b*4+jj] + p1z[64+b*4+jj] + axz + bz1[jj];
                float pr = p1r[b*4+jj] + p1r[64+b*4+jj] + axr + br1[jj];
                float z = 1.0f / (1.0f + __expf(-pz));
                float r = 1.0f / (1.0f + __expf(-pr));
                float ho = T1[b*HP + j0 + jj];
                z1s[tid] = z; h1s[tid] = ho; axrs[tid] = axr;
                __stcg(&g_rh1[(b << 9) + j0 + jj], r * ho);
            }
        }
        gbar(target); target += NCTA;

        // ===== phase B: g, h_new (both layers) =====
        if (L0) load_tile(T0, g_rh0, tid);
        if (L1) load_tile(T1, g_rh1, tid);
        __syncthreads();

        if (L0) {
            float a[4] = {0,0,0,0};
            mv_one(T0, wr0, jw, fbase, bq, a);
            red_one(p0z, a, ksub, khi, bq, jw);
        }
        if (L1) {
            float a[4] = {0,0,0,0};
            mv_one(T1, wr1, jw, fbase, bq, a);
            red_one(p1z, a, ksub, khi, bq, jw);
        }
        __syncthreads();

        if (tid < 64) {
            const int b = tid >> 2, jj = tid & 3;
            if (L0) {
                float pg = p0z[b*4+jj] + p0z[64+b*4+jj] + xr0s[tid] + br0[jj];
                float g = tanhf(pg);
                float z = z0s[tid];
                float hn = z * h0s[tid] + (1.0f - z) * g;
                __stcg(&g_h0v[(b << 9) + j0 + jj], hn);   // == y0[t]
                if (t == S_LEN - 1) hf[(b << 10) + j0 + jj] = hn;
            }
            if (L1) {
                float pg = p1z[b*4+jj] + p1z[64+b*4+jj] + axrs[tid] + br1[jj];
                float g = tanhf(pg);
                float z = z1s[tid];
                float hn = z * h1s[tid] + (1.0f - z) * g;
                __stcg(&g_h1v[(b << 9) + j0 + jj], hn);
                g_y1[((size_t)(b * S_LEN + (t-1)) << 9) + j0 + jj] = hn;
                if (t == S_LEN) hf[(b << 10) + 512 + j0 + jj] = hn;
            }
        }
        gbar(target); target += NCTA;
    }
}

extern "C" void kernel_launch(void* const* d_in, const int* in_sizes, int n_in,
                              void* d_out, int out_size)
{
    (void)in_sizes; (void)n_in; (void)out_size;
    const float* x    = (const float*)d_in[0];
    const float* hst  = (const float*)d_in[1];
    const float* Wxz0 = (const float*)d_in[2];
    const float* Whz0 = (const float*)d_in[3];
    const float* bhz0 = (const float*)d_in[4];
    const float* Wxr0 = (const float*)d_in[5];
    const float* Whr0 = (const float*)d_in[6];
    const float* bhr0 = (const float*)d_in[7];
    const float* Wxz1 = (const float*)d_in[8];
    const float* Whz1 = (const float*)d_in[9];
    const float* bhz1 = (const float*)d_in[10];
    const float* Wxr1 = (const float*)d_in[11];
    const float* Whr1 = (const float*)d_in[12];
    const float* bhr1 = (const float*)d_in[13];
    const float* Why  = (const float*)d_in[14];
    const float* by   = (const float*)d_in[15];
    float* out = (float*)d_out;

    float *pz, *pr, *y1;
    cudaGetSymbolAddress((void**)&pz, g_pz);
    cudaGetSymbolAddress((void**)&pr, g_pr);
    cudaGetSymbolAddress((void**)&y1, g_y1);

    const int GRU_SMEM = (2*BATCH*HP + 6*JS*HP + 6*128 + 7*64 + 16) * 4;
    cudaFuncSetAttribute(gru_pipe_kernel,
                         cudaFuncAttributeMaxDynamicSharedMemorySize, GRU_SMEM);

    const int M = BATCH * S_LEN;                        // 32768
    float* hf = out + (size_t)BATCH * S_LEN * OUT_DIM;  // h_final [B,2,H]
    dim3 thr(256);

    // layer-0 input projections (K = 128), off the critical path
    gemm_abt_kernel<<<dim3(HID/128, M/128), thr>>>(x, Wxz0, nullptr, pz, M, HID, IN_DIM);
    gemm_abt_kernel<<<dim3(HID/128, M/128), thr>>>(x, Wxr0, nullptr, pr, M, HID, IN_DIM);
    init_kernel<<<32, 256>>>(hst);

    // fused pipelined recurrence (both layers, 2049 rounds)
    gru_pipe_kernel<<<NCTA, thr, GRU_SMEM>>>(pz, pr,
        Whz0, bhz0, Whr0, bhr0,
        Wxz1, Whz1, bhz1, Wxr1, Whr1, bhr1, hf);

    // output head: out = y1 @ Why^T + by
    gemm_abt_kernel<<<dim3(OUT_DIM/128, M/128), thr>>>(y1, Why, by, out, M, OUT_DIM, HID);
}

// round 7
// speedup vs baseline: 1.6493x; 1.0085x over previous
#include <cuda_runtime.h>
#include <cstdint>

#define S_LEN   2048
#define BATCH   16
#define HID     512
#define IN_DIM  128
#define OUT_DIM 128
#define NCTA    128
#define JS      4
#define HP      520
#define NTHR    512

// ---- scratch: device globals only ----
__device__ float g_pz [(size_t)BATCH * S_LEN * HID];
__device__ float g_pr [(size_t)BATCH * S_LEN * HID];
__device__ float g_y1 [(size_t)BATCH * S_LEN * HID];
__device__ float g_h0v[BATCH * HID];
__device__ float g_h1v[BATCH * HID];
__device__ float g_rh0[BATCH * HID];
__device__ float g_rh1[BATCH * HID];
__device__ unsigned int g_bar32;

// packed fp32x2 FMA (FFMA2) — only reachable via PTX
__device__ __forceinline__ void ffma2(unsigned long long& d,
                                      unsigned long long a, unsigned long long b) {
    asm volatile("fma.rn.f32x2 %0, %1, %2, %0;" : "+l"(d) : "l"(a), "l"(b));
}
__device__ __forceinline__ float hsum2(unsigned long long a) {
    return __uint_as_float((unsigned)a) + __uint_as_float((unsigned)(a >> 32));
}

__global__ void init_kernel(const float* __restrict__ hst) {
    int i = blockIdx.x * blockDim.x + threadIdx.x;
    if (i == 0) g_bar32 = 0;
    if (i < BATCH * HID) {
        int b = i >> 9, j = i & 511;
        g_h0v[i] = hst[(b << 10) + j];
        g_h1v[i] = hst[(b << 10) + 512 + j];
    }
}

// C[M,N] = A[M,K] @ B[N,K]^T (+bias). 128x128 tile, BK=16, 8x8 microtile.
__global__ __launch_bounds__(256, 2) void gemm_abt_kernel(
    const float* __restrict__ A, const float* __restrict__ B,
    const float* __restrict__ bias, float* __restrict__ C,
    int M, int N, int K)
{
    __shared__ __align__(16) float As[16][132];
    __shared__ __align__(16) float Bs[16][132];
    const int t = threadIdx.x, tx = t & 15, ty = t >> 4;
    const int m0 = blockIdx.y * 128, n0 = blockIdx.x * 128;
    const float* Ab = A + (size_t)m0 * K;
    const float* Bb = B + (size_t)n0 * K;

    float acc[8][8];
#pragma unroll
    for (int i = 0; i < 8; i++)
#pragma unroll
        for (int j = 0; j < 8; j++) acc[i][j] = 0.0f;

    for (int k0 = 0; k0 < K; k0 += 16) {
#pragma unroll
        for (int u = 0; u < 2; u++) {
            int f = t + 256 * u, r = f >> 2, c4 = f & 3;
            float4 va = *(const float4*)(Ab + (size_t)r * K + k0 + c4 * 4);
            As[c4*4+0][r] = va.x; As[c4*4+1][r] = va.y;
            As[c4*4+2][r] = va.z; As[c4*4+3][r] = va.w;
            float4 vb = *(const float4*)(Bb + (size_t)r * K + k0 + c4 * 4);
            Bs[c4*4+0][r] = vb.x; Bs[c4*4+1][r] = vb.y;
            Bs[c4*4+2][r] = vb.z; Bs[c4*4+3][r] = vb.w;
        }
        __syncthreads();
#pragma unroll
        for (int k = 0; k < 16; k++) {
            float rm[8], rn[8];
            *(float4*)&rm[0] = *(const float4*)&As[k][ty*8];
            *(float4*)&rm[4] = *(const float4*)&As[k][ty*8+4];
            *(float4*)&rn[0] = *(const float4*)&Bs[k][tx*8];
            *(float4*)&rn[4] = *(const float4*)&Bs[k][tx*8+4];
#pragma unroll
            for (int i = 0; i < 8; i++)
#pragma unroll
                for (int j = 0; j < 8; j++)
                    acc[i][j] = fmaf(rm[i], rn[j], acc[i][j]);
        }
        __syncthreads();
    }
    float bv[8];
#pragma unroll
    for (int j = 0; j < 8; j++) bv[j] = bias ? bias[n0 + tx*8 + j] : 0.0f;
#pragma unroll
    for (int i = 0; i < 8; i++) {
        float* cp = C + (size_t)(m0 + ty*8 + i) * N + n0 + tx*8;
        float4 o0, o1;
        o0.x = acc[i][0]+bv[0]; o0.y = acc[i][1]+bv[1];
        o0.z = acc[i][2]+bv[2]; o0.w = acc[i][3]+bv[3];
        o1.x = acc[i][4]+bv[4]; o1.y = acc[i][5]+bv[5];
        o1.z = acc[i][6]+bv[6]; o1.w = acc[i][7]+bv[7];
        *(float4*)cp = o0; *(float4*)(cp+4) = o1;
    }
}

// ---- fused matvec + cross-lane reduce + partial store (512-thread map) ----
// lane: jw=lane&3, ksub=lane>>2; warp(16): bq=w>>2 (4 batch groups), khi=w&3.
// k chunks: f4 = ksub + 8*khi + 32*kk, kk 0..3 -> 128 float4 = 512 k.
__device__ __forceinline__ void mv_red_pair(const float* __restrict__ T,
    const float* __restrict__ wA, const float* __restrict__ wB,
    float* qA, float* qB, int jw, int ksub, int bq, int khi, int fbase)
{
    unsigned long long aA[4] = {0,0,0,0}, aB[4] = {0,0,0,0};
#pragma unroll
    for (int kk = 0; kk < 4; kk++) {
        const int fo = (fbase + 32*kk) * 4;
        ulonglong2 wa = *(const ulonglong2*)&wA[jw*HP + fo];
        ulonglong2 wb = *(const ulonglong2*)&wB[jw*HP + fo];
#pragma unroll
        for (int i = 0; i < 4; i++) {
            ulonglong2 hv = *(const ulonglong2*)&T[(bq*4+i)*HP + fo];
            ffma2(aA[i], hv.x, wa.x); ffma2(aA[i], hv.y, wa.y);
            ffma2(aB[i], hv.x, wb.x); ffma2(aB[i], hv.y, wb.y);
        }
    }
    float sA[4], sB[4];
#pragma unroll
    for (int i = 0; i < 4; i++) { sA[i] = hsum2(aA[i]); sB[i] = hsum2(aB[i]); }
#pragma unroll
    for (int off = 4; off < 32; off <<= 1)
#pragma unroll
        for (int i = 0; i < 4; i++) {
            sA[i] += __shfl_xor_sync(0xffffffffu, sA[i], off);
            sB[i] += __shfl_xor_sync(0xffffffffu, sB[i], off);
        }
    if (ksub == 0)
#pragma unroll
        for (int i = 0; i < 4; i++) {
            qA[khi*64 + (bq*4+i)*4 + jw] = sA[i];
            qB[khi*64 + (bq*4+i)*4 + jw] = sB[i];
        }
}
__device__ __forceinline__ void mv_red_one(const float* __restrict__ T,
    const float* __restrict__ wA, float* qA,
    int jw, int ksub, int bq, int khi, int fbase)
{
    unsigned long long aA[4] = {0,0,0,0};
#pragma unroll
    for (int kk = 0; kk < 4; kk++) {
        const int fo = (fbase + 32*kk) * 4;
        ulonglong2 wa = *(const ulonglong2*)&wA[jw*HP + fo];
#pragma unroll
        for (int i = 0; i < 4; i++) {
            ulonglong2 hv = *(const ulonglong2*)&T[(bq*4+i)*HP + fo];
            ffma2(aA[i], hv.x, wa.x); ffma2(aA[i], hv.y, wa.y);
        }
    }
    float sA[4];
#pragma unroll
    for (int i = 0; i < 4; i++) sA[i] = hsum2(aA[i]);
#pragma unroll
    for (int off = 4; off < 32; off <<= 1)
#pragma unroll
        for (int i = 0; i < 4; i++)
            sA[i] += __shfl_xor_sync(0xffffffffu, sA[i], off);
    if (ksub == 0)
#pragma unroll
        for (int i = 0; i < 4; i++)
            qA[khi*64 + (bq*4+i)*4 + jw] = sA[i];
}
__device__ __forceinline__ float q4sum(const float* q, int idx) {
    return q[idx] + q[64+idx] + q[128+idx] + q[192+idx];
}
__device__ __forceinline__ void load_tile(float* T, const float* g, int tid) {
#pragma unroll
    for (int u = 0; u < 4; u++) {
        int f = tid + NTHR*u, b = f >> 7, c = f & 127;
        float4 v = __ldcg((const float4*)g + f);
        *(float4*)&T[b*HP + c*4] = v;
    }
}

// ---- fused 2-layer pipelined GRU, 2049 rounds; z-matvecs overlap barrier-1 ----
__global__ __launch_bounds__(NTHR, 1) void gru_pipe_kernel(
    const float* __restrict__ pz0, const float* __restrict__ pr0,
    const float* __restrict__ Whz0, const float* __restrict__ bhz0,
    const float* __restrict__ Whr0, const float* __restrict__ bhr0,
    const float* __restrict__ Wxz1, const float* __restrict__ Whz1,
    const float* __restrict__ bhz1, const float* __restrict__ Wxr1,
    const float* __restrict__ Whr1, const float* __restrict__ bhr1,
    float* __restrict__ hf)
{
    extern __shared__ float sm[];
    float* T0   = sm;                  // [16][HP]
    float* T1   = T0 + BATCH*HP;
    float* wz0  = T1 + BATCH*HP;       // [4][HP] x6
    float* wr0  = wz0 + JS*HP;
    float* wz1  = wr0 + JS*HP;
    float* wr1  = wz1 + JS*HP;
    float* wxz  = wr1 + JS*HP;
    float* wxr  = wxz + JS*HP;
    float* q0   = wxr + JS*HP;         // [4][16][4] partials x6
    float* q1   = q0 + 256;
    float* q2   = q1 + 256;
    float* q3   = q2 + 256;
    float* q4   = q3 + 256;
    float* q5   = q4 + 256;
    float* z0s  = q5 + 256;            // [64] each
    float* h0s  = z0s + 64;
    float* z1s  = h0s + 64;
    float* h1s  = z1s + 64;
    float* axrs = h1s + 64;
    float* xz0s = axrs + 64;
    float* xr0s = xz0s + 64;
    float* bz0  = xr0s + 64;           // [4] each
    float* br0  = bz0 + 4;
    float* bz1  = br0 + 4;
    float* br1  = bz1 + 4;

    const int tid = threadIdx.x;
    const int j0  = blockIdx.x * JS;
    const int lane = tid & 31, wrp = tid >> 5;
    const int jw = lane & 3, ksub = lane >> 2;
    const int bq = wrp >> 2, khi = wrp & 3;
    const int fbase = ksub + 8 * khi;

    for (int idx = tid; idx < JS * HID; idx += NTHR) {
        int jj = idx >> 9, k = idx & 511;
        size_t w = (size_t)(j0 + jj) * HID + k;
        int s = jj * HP + k;
        wz0[s] = Whz0[w]; wr0[s] = Whr0[w];
        wz1[s] = Whz1[w]; wr1[s] = Whr1[w];
        wxz[s] = Wxz1[w]; wxr[s] = Wxr1[w];
    }
    if (tid < JS) {
        bz0[tid] = bhz0[j0+tid]; br0[tid] = bhr0[j0+tid];
        bz1[tid] = bhz1[j0+tid]; br1[tid] = bhr1[j0+tid];
    }

    unsigned int target = NCTA;
    unsigned int* barp = &g_bar32;

    for (int t = 0; t <= S_LEN; t++) {
        const bool L0 = (t < S_LEN);
        const bool L1 = (t >= 1);

        // ===== phase A: r gates (both layers) + layer1 xr projection =====
        load_tile(T0, g_h0v, tid);          // h0 == y0[t-1]
        if (L1) load_tile(T1, g_h1v, tid);
        if (L0 && tid < BATCH) {
            size_t off = ((size_t)(tid * S_LEN + t) << 9) + j0;
            *(float4*)&xz0s[tid*4] = *(const float4*)(pz0 + off);
            *(float4*)&xr0s[tid*4] = *(const float4*)(pr0 + off);
        }
        __syncthreads();

        if (L0) {
            if (L1) mv_red_pair(T0, wr0, wxr, q0, q1, jw, ksub, bq, khi, fbase);
            else    mv_red_one (T0, wr0, q0, jw, ksub, bq, khi, fbase);
        } else      mv_red_one (T0, wxr, q1, jw, ksub, bq, khi, fbase);
        if (L1)     mv_red_one (T1, wr1, q2, jw, ksub, bq, khi, fbase);
        __syncthreads();

        if (tid < 64) {
            const int b = tid >> 2, jj = tid & 3;
            if (L0) {
                float pr = q4sum(q0, tid) + xr0s[tid] + br0[jj];
                float r  = 1.0f / (1.0f + __expf(-pr));
                float ho = T0[b*HP + j0 + jj];
                h0s[tid] = ho;
                __stcg(&g_rh0[(b << 9) + j0 + jj], r * ho);
            }
            if (L1) {
                float axr = q4sum(q1, tid);
                float pr  = q4sum(q2, tid) + axr + br1[jj];
                float r   = 1.0f / (1.0f + __expf(-pr));
                float ho  = T1[b*HP + j0 + jj];
                h1s[tid] = ho; axrs[tid] = axr;
                __stcg(&g_rh1[(b << 9) + j0 + jj], r * ho);
            }
        }
        __syncthreads();
        if (tid == 0)
            asm volatile("red.release.gpu.add.u32 [%0], %1;" :: "l"(barp), "r"(1u) : "memory");

        // ===== z gates, overlapping barrier-1 propagation =====
        if (L0) {
            if (L1) mv_red_pair(T0, wz0, wxz, q3, q4, jw, ksub, bq, khi, fbase);
            else    mv_red_one (T0, wz0, q3, jw, ksub, bq, khi, fbase);
        } else      mv_red_one (T0, wxz, q4, jw, ksub, bq, khi, fbase);
        if (L1)     mv_red_one (T1, wz1, q5, jw, ksub, bq, khi, fbase);
        __syncthreads();

        if (tid < 64) {
            const int jj = tid & 3;
            if (L0) {
                float pz = q4sum(q3, tid) + xz0s[tid] + bz0[jj];
                z0s[tid] = 1.0f / (1.0f + __expf(-pz));
            }
            if (L1) {
                float pz = q4sum(q5, tid) + q4sum(q4, tid) + bz1[jj];
                z1s[tid] = 1.0f / (1.0f + __expf(-pz));
            }
        }
        if (tid == 0) {          // wait barrier-1
            unsigned int v;
            do { asm volatile("ld.acquire.gpu.u32 %0, [%1];" : "=r"(v) : "l"(barp) : "memory"); }
            while (v < target);
        }
        target += NCTA;
        __syncthreads();

        // ===== phase B: candidate g, h_new (both layers) =====
        if (L0) load_tile(T0, g_rh0, tid);
        if (L1) load_tile(T1, g_rh1, tid);
        __syncthreads();

        if (L0) mv_red_one(T0, wr0, q0, jw, ksub, bq, khi, fbase);
        if (L1) mv_red_one(T1, wr1, q2, jw, ksub, bq, khi, fbase);
        __syncthreads();

        if (tid < 64) {
            const int b = tid >> 2, jj = tid & 3;
            if (L0) {
                float pg = q4sum(q0, tid) + xr0s[tid] + br0[jj];
                float g  = tanhf(pg);
                float z  = z0s[tid];
                float hn = z * h0s[tid] + (1.0f - z) * g;
                __stcg(&g_h0v[(b << 9) + j0 + jj], hn);       // == y0[t]
                if (t == S_LEN - 1) hf[(b << 10) + j0 + jj] = hn;
            }
            if (L1) {
                float pg = q4sum(q2, tid) + axrs[tid] + br1[jj];
                float g  = tanhf(pg);
                float z  = z1s[tid];
                float hn = z * h1s[tid] + (1.0f - z) * g;
                __stcg(&g_h1v[(b << 9) + j0 + jj], hn);
                g_y1[((size_t)(b * S_LEN + (t-1)) << 9) + j0 + jj] = hn;
                if (t == S_LEN) hf[(b << 10) + 512 + j0 + jj] = hn;
            }
        }
        __syncthreads();
        if (tid == 0) {
            asm volatile("red.release.gpu.add.u32 [%0], %1;" :: "l"(barp), "r"(1u) : "memory");
            unsigned int v;
            do { asm volatile("ld.acquire.gpu.u32 %0, [%1];" : "=r"(v) : "l"(barp) : "memory"); }
            while (v < target);
        }
        target += NCTA;
        __syncthreads();
    }
}

extern "C" void kernel_launch(void* const* d_in, const int* in_sizes, int n_in,
                              void* d_out, int out_size)
{
    (void)in_sizes; (void)n_in; (void)out_size;
    const float* x    = (const float*)d_in[0];
    const float* hst  = (const float*)d_in[1];
    const float* Wxz0 = (const float*)d_in[2];
    const float* Whz0 = (const float*)d_in[3];
    const float* bhz0 = (const float*)d_in[4];
    const float* Wxr0 = (const float*)d_in[5];
    const float* Whr0 = (const float*)d_in[6];
    const float* bhr0 = (const float*)d_in[7];
    const float* Wxz1 = (const float*)d_in[8];
    const float* Whz1 = (const float*)d_in[9];
    const float* bhz1 = (const float*)d_in[10];
    const float* Wxr1 = (const float*)d_in[11];
    const float* Whr1 = (const float*)d_in[12];
    const float* bhr1 = (const float*)d_in[13];
    const float* Why  = (const float*)d_in[14];
    const float* by   = (const float*)d_in[15];
    float* out = (float*)d_out;

    float *pz, *pr, *y1;
    cudaGetSymbolAddress((void**)&pz, g_pz);
    cudaGetSymbolAddress((void**)&pr, g_pr);
    cudaGetSymbolAddress((void**)&y1, g_y1);

    const int GRU_SMEM = (2*BATCH*HP + 6*JS*HP + 6*256 + 7*64 + 16) * 4;
    cudaFuncSetAttribute(gru_pipe_kernel,
                         cudaFuncAttributeMaxDynamicSharedMemorySize, GRU_SMEM);

    const int M = BATCH * S_LEN;                        // 32768
    float* hf = out + (size_t)BATCH * S_LEN * OUT_DIM;  // h_final [B,2,H]

    // layer-0 input projections (K = 128), off the critical path
    gemm_abt_kernel<<<dim3(HID/128, M/128), 256>>>(x, Wxz0, nullptr, pz, M, HID, IN_DIM);
    gemm_abt_kernel<<<dim3(HID/128, M/128), 256>>>(x, Wxr0, nullptr, pr, M, HID, IN_DIM);
    init_kernel<<<32, 256>>>(hst);

    // fused pipelined recurrence (both layers, 2049 rounds)
    gru_pipe_kernel<<<NCTA, NTHR, GRU_SMEM>>>(pz, pr,
        Whz0, bhz0, Whr0, bhr0,
        Wxz1, Whz1, bhz1, Wxr1, Whr1, bhr1, hf);

    // output head: out = y1 @ Why^T + by
    gemm_abt_kernel<<<dim3(OUT_DIM/128, M/128), 256>>>(y1, Why, by, out, M, OUT_DIM, HID);
}

// round 8
// speedup vs baseline: 1.7474x; 1.0595x over previous
#include <cuda_runtime.h>
#include <cstdint>

#define S_LEN   2048
#define BATCH   16
#define HID     512
#define IN_DIM  128
#define OUT_DIM 128
#define NCTA    128
#define JS      4
#define HP      520

// ---- scratch: device globals only ----
__device__ float g_pz [(size_t)BATCH * S_LEN * HID];
__device__ float g_pr [(size_t)BATCH * S_LEN * HID];
__device__ float g_y1 [(size_t)BATCH * S_LEN * HID];
__device__ float g_h0v[BATCH * HID];
__device__ float g_h1v[BATCH * HID];
__device__ float g_rh0[BATCH * HID];
__device__ float g_rh1[BATCH * HID];
__device__ unsigned int g_ctr[128];   // 4 counters at 0,32,64,96 (128B apart)

__device__ __forceinline__ void ctr_rel(unsigned int* p) {
    asm volatile("red.release.gpu.add.u32 [%0], %1;" :: "l"(p), "r"(1u) : "memory");
}
__device__ __forceinline__ void ctr_poll(unsigned int* p, unsigned int target) {
    unsigned int v;
    do { asm volatile("ld.acquire.gpu.u32 %0, [%1];" : "=r"(v) : "l"(p) : "memory"); }
    while (v < target);
}
__device__ __forceinline__ void ffma2(unsigned long long& d,
                                      unsigned long long a, unsigned long long b) {
    asm volatile("fma.rn.f32x2 %0, %1, %2, %0;" : "+l"(d) : "l"(a), "l"(b));
}
__device__ __forceinline__ float hsum2(unsigned long long a) {
    return __uint_as_float((unsigned)a) + __uint_as_float((unsigned)(a >> 32));
}
// gang-local named barriers (256 threads each)
__device__ __forceinline__ void barg(int id) {
    asm volatile("bar.sync %0, 256;" :: "r"(id) : "memory");
}

__global__ void init_kernel(const float* __restrict__ hst) {
    int i = blockIdx.x * blockDim.x + threadIdx.x;
    if (i < 128) g_ctr[i] = 0;
    if (i < BATCH * HID) {
        int b = i >> 9, j = i & 511;
        g_h0v[i] = hst[(b << 10) + j];
        g_h1v[i] = hst[(b << 10) + 512 + j];
    }
}

// C[M,N] = A[M,K] @ B[N,K]^T (+bias). 128x128 tile, BK=16, 8x8 microtile.
__global__ __launch_bounds__(256, 2) void gemm_abt_kernel(
    const float* __restrict__ A, const float* __restrict__ B,
    const float* __restrict__ bias, float* __restrict__ C,
    int M, int N, int K)
{
    __shared__ __align__(16) float As[16][132];
    __shared__ __align__(16) float Bs[16][132];
    const int t = threadIdx.x, tx = t & 15, ty = t >> 4;
    const int m0 = blockIdx.y * 128, n0 = blockIdx.x * 128;
    const float* Ab = A + (size_t)m0 * K;
    const float* Bb = B + (size_t)n0 * K;

    float acc[8][8];
#pragma unroll
    for (int i = 0; i < 8; i++)
#pragma unroll
        for (int j = 0; j < 8; j++) acc[i][j] = 0.0f;

    for (int k0 = 0; k0 < K; k0 += 16) {
#pragma unroll
        for (int u = 0; u < 2; u++) {
            int f = t + 256 * u, r = f >> 2, c4 = f & 3;
            float4 va = *(const float4*)(Ab + (size_t)r * K + k0 + c4 * 4);
            As[c4*4+0][r] = va.x; As[c4*4+1][r] = va.y;
            As[c4*4+2][r] = va.z; As[c4*4+3][r] = va.w;
            float4 vb = *(const float4*)(Bb + (size_t)r * K + k0 + c4 * 4);
            Bs[c4*4+0][r] = vb.x; Bs[c4*4+1][r] = vb.y;
            Bs[c4*4+2][r] = vb.z; Bs[c4*4+3][r] = vb.w;
        }
        __syncthreads();
#pragma unroll
        for (int k = 0; k < 16; k++) {
            float rm[8], rn[8];
            *(float4*)&rm[0] = *(const float4*)&As[k][ty*8];
            *(float4*)&rm[4] = *(const float4*)&As[k][ty*8+4];
            *(float4*)&rn[0] = *(const float4*)&Bs[k][tx*8];
            *(float4*)&rn[4] = *(const float4*)&Bs[k][tx*8+4];
#pragma unroll
            for (int i = 0; i < 8; i++)
#pragma unroll
                for (int j = 0; j < 8; j++)
                    acc[i][j] = fmaf(rm[i], rn[j], acc[i][j]);
        }
        __syncthreads();
    }
    float bv[8];
#pragma unroll
    for (int j = 0; j < 8; j++) bv[j] = bias ? bias[n0 + tx*8 + j] : 0.0f;
#pragma unroll
    for (int i = 0; i < 8; i++) {
        float* cp = C + (size_t)(m0 + ty*8 + i) * N + n0 + tx*8;
        float4 o0, o1;
        o0.x = acc[i][0]+bv[0]; o0.y = acc[i][1]+bv[1];
        o0.z = acc[i][2]+bv[2]; o0.w = acc[i][3]+bv[3];
        o1.x = acc[i][4]+bv[4]; o1.y = acc[i][5]+bv[5];
        o1.z = acc[i][6]+bv[6]; o1.w = acc[i][7]+bv[7];
        *(float4*)cp = o0; *(float4*)(cp+4) = o1;
    }
}

// ---- gang matvec map: 8 warps (256 thr) per gang ----
// lane: jw=lane&3, ksub=lane>>2; warp w8(0..7): bq=w8>>1, khi=w8&1.
// k float4 index: f4 = ksub + 8*khi + 16*kk, kk=0..7 -> 128 float4 = 512 k.
// Partials q[2][16][4]; q2sum(q,idx)=q[idx]+q[64+idx].
__device__ __forceinline__ void mv_quad(const float* __restrict__ T,
    const float* __restrict__ w0, const float* __restrict__ w1,
    const float* __restrict__ w2, const float* __restrict__ w3,
    float* q0, float* q1, float* q2, float* q3,
    int jw, int ksub, int bq, int khi, int fbase)
{
    unsigned long long a0[4]={0,0,0,0}, a1[4]={0,0,0,0},
                       a2[4]={0,0,0,0}, a3[4]={0,0,0,0};
#pragma unroll
    for (int kk = 0; kk < 8; kk++) {
        const int fo = (fbase + 16*kk) * 4;
        ulonglong2 wa = *(const ulonglong2*)&w0[jw*HP + fo];
        ulonglong2 wb = *(const ulonglong2*)&w1[jw*HP + fo];
        ulonglong2 wc = *(const ulonglong2*)&w2[jw*HP + fo];
        ulonglong2 wd = *(const ulonglong2*)&w3[jw*HP + fo];
#pragma unroll
        for (int i = 0; i < 4; i++) {
            ulonglong2 hv = *(const ulonglong2*)&T[(bq*4+i)*HP + fo];
            ffma2(a0[i], hv.x, wa.x); ffma2(a0[i], hv.y, wa.y);
            ffma2(a1[i], hv.x, wb.x); ffma2(a1[i], hv.y, wb.y);
            ffma2(a2[i], hv.x, wc.x); ffma2(a2[i], hv.y, wc.y);
            ffma2(a3[i], hv.x, wd.x); ffma2(a3[i], hv.y, wd.y);
        }
    }
    float s0[4], s1[4], s2[4], s3[4];
#pragma unroll
    for (int i = 0; i < 4; i++) {
        s0[i]=hsum2(a0[i]); s1[i]=hsum2(a1[i]); s2[i]=hsum2(a2[i]); s3[i]=hsum2(a3[i]);
    }
#pragma unroll
    for (int off = 4; off < 32; off <<= 1)
#pragma unroll
        for (int i = 0; i < 4; i++) {
            s0[i] += __shfl_xor_sync(0xffffffffu, s0[i], off);
            s1[i] += __shfl_xor_sync(0xffffffffu, s1[i], off);
            s2[i] += __shfl_xor_sync(0xffffffffu, s2[i], off);
            s3[i] += __shfl_xor_sync(0xffffffffu, s3[i], off);
        }
    if (ksub == 0)
#pragma unroll
        for (int i = 0; i < 4; i++) {
            int o = khi*64 + (bq*4+i)*4 + jw;
            q0[o] = s0[i]; q1[o] = s1[i]; q2[o] = s2[i]; q3[o] = s3[i];
        }
}
__device__ __forceinline__ void mv_pair(const float* __restrict__ T,
    const float* __restrict__ w0, const float* __restrict__ w1,
    float* q0, float* q1, int jw, int ksub, int bq, int khi, int fbase)
{
    unsigned long long a0[4]={0,0,0,0}, a1[4]={0,0,0,0};
#pragma unroll
    for (int kk = 0; kk < 8; kk++) {
        const int fo = (fbase + 16*kk) * 4;
        ulonglong2 wa = *(const ulonglong2*)&w0[jw*HP + fo];
        ulonglong2 wb = *(const ulonglong2*)&w1[jw*HP + fo];
#pragma unroll
        for (int i = 0; i < 4; i++) {
            ulonglong2 hv = *(const ulonglong2*)&T[(bq*4+i)*HP + fo];
            ffma2(a0[i], hv.x, wa.x); ffma2(a0[i], hv.y, wa.y);
            ffma2(a1[i], hv.x, wb.x); ffma2(a1[i], hv.y, wb.y);
        }
    }
    float s0[4], s1[4];
#pragma unroll
    for (int i = 0; i < 4; i++) { s0[i]=hsum2(a0[i]); s1[i]=hsum2(a1[i]); }
#pragma unroll
    for (int off = 4; off < 32; off <<= 1)
#pragma unroll
        for (int i = 0; i < 4; i++) {
            s0[i] += __shfl_xor_sync(0xffffffffu, s0[i], off);
            s1[i] += __shfl_xor_sync(0xffffffffu, s1[i], off);
        }
    if (ksub == 0)
#pragma unroll
        for (int i = 0; i < 4; i++) {
            int o = khi*64 + (bq*4+i)*4 + jw;
            q0[o] = s0[i]; q1[o] = s1[i];
        }
}
__device__ __forceinline__ void mv_one(const float* __restrict__ T,
    const float* __restrict__ w0, float* q0,
    int jw, int ksub, int bq, int khi, int fbase)
{
    unsigned long long a0[4]={0,0,0,0};
#pragma unroll
    for (int kk = 0; kk < 8; kk++) {
        const int fo = (fbase + 16*kk) * 4;
        ulonglong2 wa = *(const ulonglong2*)&w0[jw*HP + fo];
#pragma unroll
        for (int i = 0; i < 4; i++) {
            ulonglong2 hv = *(const ulonglong2*)&T[(bq*4+i)*HP + fo];
            ffma2(a0[i], hv.x, wa.x); ffma2(a0[i], hv.y, wa.y);
        }
    }
    float s0[4];
#pragma unroll
    for (int i = 0; i < 4; i++) s0[i] = hsum2(a0[i]);
#pragma unroll
    for (int off = 4; off < 32; off <<= 1)
#pragma unroll
        for (int i = 0; i < 4; i++)
            s0[i] += __shfl_xor_sync(0xffffffffu, s0[i], off);
    if (ksub == 0)
#pragma unroll
        for (int i = 0; i < 4; i++)
            q0[khi*64 + (bq*4+i)*4 + jw] = s0[i];
}
__device__ __forceinline__ float q2sum(const float* q, int idx) {
    return q[idx] + q[64+idx];
}
__device__ __forceinline__ void load_tile256(float* T, const float* g, int gtid) {
#pragma unroll
    for (int u = 0; u < 8; u++) {
        int f = gtid + 256*u, b = f >> 7, c = f & 127;
        float4 v = __ldcg((const float4*)g + f);
        *(float4*)&T[b*HP + c*4] = v;
    }
}

// ---- warp-specialized 2-layer GRU: gang0 = layer0 + L1 projections, gang1 = layer1 ----
__global__ __launch_bounds__(512, 1) void gru_ws_kernel(
    const float* __restrict__ pz0, const float* __restrict__ pr0,
    const float* __restrict__ Whz0, const float* __restrict__ bhz0,
    const float* __restrict__ Whr0, const float* __restrict__ bhr0,
    const float* __restrict__ Wxz1, const float* __restrict__ Whz1,
    const float* __restrict__ bhz1, const float* __restrict__ Wxr1,
    const float* __restrict__ Whr1, const float* __restrict__ bhr1,
    float* __restrict__ hf)
{
    extern __shared__ float sm[];
    float* T0   = sm;                  // [16][HP] gang0 tile (h0 / rh0)
    float* T1   = T0 + BATCH*HP;       // [16][HP] gang1 tile (h1 / rh1)
    float* wz0  = T1 + BATCH*HP;       // 6 weight slices [4][HP]
    float* wr0  = wz0 + JS*HP;
    float* wz1  = wr0 + JS*HP;
    float* wr1  = wz1 + JS*HP;
    float* wxz  = wr1 + JS*HP;
    float* wxr  = wxz + JS*HP;
    float* q0   = wxr + JS*HP;         // partials [128] x6
    float* q1   = q0 + 128;
    float* q2   = q1 + 128;
    float* q3   = q2 + 128;
    float* q4   = q3 + 128;
    float* q5   = q4 + 128;
    float* z0s  = q5 + 128;            // [64] each
    float* h0s  = z0s + 64;
    float* xz0s = h0s + 64;
    float* xr0s = xz0s + 64;
    float* z1s  = xr0s + 64;
    float* h1s  = z1s + 64;
    float* axrs = h1s + 64;
    float* axr2 = axrs + 64;           // [2][64] double-buffered handoff
    float* axz2 = axr2 + 128;          // [2][64]
    float* bz0  = axz2 + 128;          // [4] each
    float* br0  = bz0 + 4;
    float* bz1  = br0 + 4;
    float* br1  = bz1 + 4;
    volatile int* flags = (volatile int*)(br1 + 4);  // [0]=l0_axr_done, [1]=l1_done

    const int tid  = threadIdx.x;
    const int gang = tid >> 8;
    const int gtid = tid & 255;
    const int j0   = blockIdx.x * JS;
    const int lane = tid & 31;
    const int w8   = (tid >> 5) & 7;
    const int jw = lane & 3, ksub = lane >> 2;
    const int bq = w8 >> 1, khi = w8 & 1;
    const int fbase = ksub + 8 * khi;

    for (int idx = tid; idx < JS * HID; idx += 512) {
        int jj = idx >> 9, k = idx & 511;
        size_t w = (size_t)(j0 + jj) * HID + k;
        int s = jj * HP + k;
        wz0[s] = Whz0[w]; wr0[s] = Whr0[w];
        wz1[s] = Whz1[w]; wr1[s] = Whr1[w];
        wxz[s] = Wxz1[w]; wxr[s] = Wxr1[w];
    }
    if (tid < JS) {
        bz0[tid] = bhz0[j0+tid]; br0[tid] = bhr0[j0+tid];
        bz1[tid] = bhz1[j0+tid]; br1[tid] = bhr1[j0+tid];
    }
    if (tid == 0) { flags[0] = 0; flags[1] = 0; }
    __syncthreads();

    unsigned int* C_RH0 = &g_ctr[0];
    unsigned int* C_H0  = &g_ctr[32];
    unsigned int* C_RH1 = &g_ctr[64];
    unsigned int* C_H1  = &g_ctr[96];

    if (gang == 0) {
        // ================= layer 0 + layer-1 input projections =================
        unsigned int tgt = NCTA;
        for (int t = 0; t <= S_LEN; t++) {
            // phase A: T0 <- h0 (== y0[t-1]); quad matvec wr0,wz0,wxr,wxz
            load_tile256(T0, g_h0v, gtid);
            if (t < S_LEN && gtid < BATCH) {
                size_t off = ((size_t)(gtid * S_LEN + t) << 9) + j0;
                *(float4*)&xz0s[gtid*4] = *(const float4*)(pz0 + off);
                *(float4*)&xr0s[gtid*4] = *(const float4*)(pr0 + off);
            }
            barg(1);
            mv_quad(T0, wr0, wz0, wxr, wxz, q0, q1, q2, q3,
                    jw, ksub, bq, khi, fbase);
            barg(1);
            if (gtid < 64) {
                const int b = gtid >> 2, jj = gtid & 3;
                if (t >= 1) {
                    // write axr/axz slot t&1 (consumed by gang1 round t);
                    // back-pressure: slot last read by gang1 at round t-2
                    while (flags[1] < t - 2) { }
                    axr2[(t&1)*64 + gtid] = q2sum(q2, gtid);
                    axz2[(t&1)*64 + gtid] = q2sum(q3, gtid);
                }
                if (t < S_LEN) {
                    float pr = q2sum(q0, gtid) + xr0s[gtid] + br0[jj];
                    float pz = q2sum(q1, gtid) + xz0s[gtid] + bz0[jj];
                    float r  = 1.0f / (1.0f + __expf(-pr));
                    z0s[gtid] = 1.0f / (1.0f + __expf(-pz));
                    float ho = T0[b*HP + j0 + jj];
                    h0s[gtid] = ho;
                    __stcg(&g_rh0[(b << 9) + j0 + jj], r * ho);
                }
            }
            barg(1);
            if (gtid == 0) {
                if (t >= 1) { __threadfence_block(); flags[0] = t; }
                if (t < S_LEN) ctr_rel(C_RH0);
            }
            if (t == S_LEN) break;   // last round only feeds gang1's projections

            // phase B: g0, h0_new
            if (gtid == 0) ctr_poll(C_RH0, tgt);
            barg(1);
            load_tile256(T0, g_rh0, gtid);
            barg(1);
            mv_one(T0, wr0, q0, jw, ksub, bq, khi, fbase);
            barg(1);
            if (gtid < 64) {
                const int b = gtid >> 2, jj = gtid & 3;
                float pg = q2sum(q0, gtid) + xr0s[gtid] + br0[jj];
                float g  = tanhf(pg);
                float z  = z0s[gtid];
                float hn = z * h0s[gtid] + (1.0f - z) * g;
                __stcg(&g_h0v[(b << 9) + j0 + jj], hn);    // == y0[t]
                if (t == S_LEN - 1) hf[(b << 10) + j0 + jj] = hn;
            }
            barg(1);
            if (gtid == 0) { ctr_rel(C_H0); ctr_poll(C_H0, tgt); }
            tgt += NCTA;
            barg(1);
        }
    } else {
        // ================= layer 1 (GRU step s = t-1) =================
        unsigned int tgt = NCTA;
        for (int t = 1; t <= S_LEN; t++) {
            load_tile256(T1, g_h1v, gtid);
            barg(2);
            mv_pair(T1, wr1, wz1, q4, q5, jw, ksub, bq, khi, fbase);
            barg(2);
            if (gtid < 64) {
                const int b = gtid >> 2, jj = gtid & 3;
                while (flags[0] < t) { }
                __threadfence_block();
                float axr = axr2[(t&1)*64 + gtid];
                float axz = axz2[(t&1)*64 + gtid];
                float pr = q2sum(q4, gtid) + axr + br1[jj];
                float pz = q2sum(q5, gtid) + axz + bz1[jj];
                float r  = 1.0f / (1.0f + __expf(-pr));
                z1s[gtid] = 1.0f / (1.0f + __expf(-pz));
                float ho = T1[b*HP + j0 + jj];
                h1s[gtid] = ho; axrs[gtid] = axr;
                __stcg(&g_rh1[(b << 9) + j0 + jj], r * ho);
            }
            barg(2);
            if (gtid == 0) {
                flags[1] = t;            // axr slot consumed
                ctr_rel(C_RH1); ctr_poll(C_RH1, tgt);
            }
            barg(2);
            load_tile256(T1, g_rh1, gtid);
            barg(2);
            mv_one(T1, wr1, q4, jw, ksub, bq, khi, fbase);
            barg(2);
            if (gtid < 64) {
                const int b = gtid >> 2, jj = gtid & 3;
                float pg = q2sum(q4, gtid) + axrs[gtid] + br1[jj];
                float g  = tanhf(pg);
                float z  = z1s[gtid];
                float hn = z * h1s[gtid] + (1.0f - z) * g;
                __stcg(&g_h1v[(b << 9) + j0 + jj], hn);
                g_y1[((size_t)(b * S_LEN + (t-1)) << 9) + j0 + jj] = hn;
                if (t == S_LEN) hf[(b << 10) + 512 + j0 + jj] = hn;
            }
            barg(2);
            if (gtid == 0) { ctr_rel(C_H1); ctr_poll(C_H1, tgt); }
            tgt += NCTA;
            barg(2);
        }
    }
}

extern "C" void kernel_launch(void* const* d_in, const int* in_sizes, int n_in,
                              void* d_out, int out_size)
{
    (void)in_sizes; (void)n_in; (void)out_size;
    const float* x    = (const float*)d_in[0];
    const float* hst  = (const float*)d_in[1];
    const float* Wxz0 = (const float*)d_in[2];
    const float* Whz0 = (const float*)d_in[3];
    const float* bhz0 = (const float*)d_in[4];
    const float* Wxr0 = (const float*)d_in[5];
    const float* Whr0 = (const float*)d_in[6];
    const float* bhr0 = (const float*)d_in[7];
    const float* Wxz1 = (const float*)d_in[8];
    const float* Whz1 = (const float*)d_in[9];
    const float* bhz1 = (const float*)d_in[10];
    const float* Wxr1 = (const float*)d_in[11];
    const float* Whr1 = (const float*)d_in[12];
    const float* bhr1 = (const float*)d_in[13];
    const float* Why  = (const float*)d_in[14];
    const float* by   = (const float*)d_in[15];
    float* out = (float*)d_out;

    float *pz, *pr, *y1;
    cudaGetSymbolAddress((void**)&pz, g_pz);
    cudaGetSymbolAddress((void**)&pr, g_pr);
    cudaGetSymbolAddress((void**)&y1, g_y1);

    const int GRU_SMEM = (2*BATCH*HP + 6*JS*HP + 6*128 + 7*64 + 2*128 + 16 + 8) * 4;
    cudaFuncSetAttribute(gru_ws_kernel,
                         cudaFuncAttributeMaxDynamicSharedMemorySize, GRU_SMEM);

    const int M = BATCH * S_LEN;                        // 32768
    float* hf = out + (size_t)BATCH * S_LEN * OUT_DIM;  // h_final [B,2,H]

    // layer-0 input projections (K = 128), off the critical path
    gemm_abt_kernel<<<dim3(HID/128, M/128), 256>>>(x, Wxz0, nullptr, pz, M, HID, IN_DIM);
    gemm_abt_kernel<<<dim3(HID/128, M/128), 256>>>(x, Wxr0, nullptr, pr, M, HID, IN_DIM);
    init_kernel<<<32, 256>>>(hst);

    // warp-specialized pipelined recurrence
    gru_ws_kernel<<<NCTA, 512, GRU_SMEM>>>(pz, pr,
        Whz0, bhz0, Whr0, bhr0,
        Wxz1, Whz1, bhz1, Wxr1, Whr1, bhr1, hf);

    // output head: out = y1 @ Why^T + by
    gemm_abt_kernel<<<dim3(OUT_DIM/128, M/128), 256>>>(y1, Why, by, out, M, OUT_DIM, HID);
}